// round 9
// baseline (speedup 1.0000x reference)
#include <cuda_runtime.h>
#include <cuda_fp16.h>
#include <math.h>

#define Bsz  2048
#define Tin  128
#define Fin  64
#define Hh   256
#define OUTL 32
#define FCH  256

typedef unsigned long long ull;

// ---------------- scratch (device globals; no allocation) ----------------
__device__ float  g_hs  [(size_t)Tin * Bsz * Hh];  // fp32 [t][b][h]
__device__ __half g_hs_h[(size_t)Tin * Bsz * Hh];  // fp16 copy (decoder stream)
__device__ float  g_A [(size_t)Bsz * Tin];
__device__ float  g_C [(size_t)Bsz * Tin];
__device__ float  g_prev[Bsz];
__device__ float  g_ctx[(size_t)Bsz * Hh];
__device__ float  g_hd [(size_t)Bsz * Hh];

__device__ __forceinline__ float sigm(float x)  { return __fdividef(1.f, 1.f + __expf(-x)); }
__device__ __forceinline__ float tanh_(float x) { return 2.f * sigm(2.f * x) - 1.f; }

__device__ __forceinline__ ull pk2(float lo, float hi) {
    ull r; asm("mov.b64 %0,{%1,%2};" : "=l"(r) : "f"(lo), "f"(hi)); return r;
}
__device__ __forceinline__ void upk2(ull v, float& lo, float& hi) {
    asm("mov.b64 {%0,%1},%2;" : "=f"(lo), "=f"(hi) : "l"(v));
}
__device__ __forceinline__ ull ffma2(ull a, ull b, ull c) {
    ull d; asm("fma.rn.f32x2 %0,%1,%2,%3;" : "=l"(d) : "l"(a), "l"(b), "l"(c)); return d;
}

// ============================================================================
// Double-buffered FFMA2 GEMM pipe: 16 batch rows x 64 u x 3 gates per CTA.
// 128 thr = 4 warps; warp owns 4 rows; lane owns u-pair. kb = 16.
// in2 rows hold activations DUPLICATED {v,v}; row stride 36 floats (144 B,
// 16B-aligned). wt stride 194.
// ============================================================================
struct PipeBuf { float in2[16][36]; float wt[16][194]; };   // 14.7 KB

template<int NB>
__device__ __forceinline__ void gemm_pipe(
    const float* __restrict__ in, int ldin,
    const float* __restrict__ W,  int ldw,  int u0,
    int tid, int warp, int lane,
    ull (&aR)[4], ull (&aZ)[4], ull (&aN)[4], PipeBuf (&sb)[2])
{
    int kq = tid & 7, row = tid >> 3;      // activation staging: float2 per thread
    float2 vin; float4 vw[6];

    auto LD = [&](int bi) {
        int kb = bi * 16;
        vin = *(const float2*)(in + (size_t)row * ldin + kb + kq * 2);
#pragma unroll
        for (int it = 0; it < 6; ++it) {
            int idx = tid + it * 128; int kw = idx & 3, col = idx >> 2;
            int g = col >> 6, u = col & 63;
            vw[it] = *(const float4*)(W + (size_t)(g * 256 + u0 + u) * ldw + kb + kw * 4);
        }
    };
    auto ST = [&](PipeBuf& b) {
        *(ull*)&b.in2[kq * 2 + 0][2 * row] = pk2(vin.x, vin.x);
        *(ull*)&b.in2[kq * 2 + 1][2 * row] = pk2(vin.y, vin.y);
#pragma unroll
        for (int it = 0; it < 6; ++it) {
            int idx = tid + it * 128; int kw = idx & 3, col = idx >> 2;
            b.wt[kw * 4 + 0][col] = vw[it].x;
            b.wt[kw * 4 + 1][col] = vw[it].y;
            b.wt[kw * 4 + 2][col] = vw[it].z;
            b.wt[kw * 4 + 3][col] = vw[it].w;
        }
    };
    auto CP = [&](PipeBuf& b) {
#pragma unroll
        for (int k = 0; k < 16; ++k) {
            ull w0 = *(const ull*)&b.wt[k][      2 * lane];
            ull w1 = *(const ull*)&b.wt[k][ 64 + 2 * lane];
            ull w2 = *(const ull*)&b.wt[k][128 + 2 * lane];
            const float* ip = &b.in2[k][warp * 8];
            ulonglong2 pA = *(const ulonglong2*)(ip + 0);
            ulonglong2 pB = *(const ulonglong2*)(ip + 4);
            ull v[4] = { pA.x, pA.y, pB.x, pB.y };
#pragma unroll
            for (int i = 0; i < 4; ++i) {
                aR[i] = ffma2(v[i], w0, aR[i]);
                aZ[i] = ffma2(v[i], w1, aZ[i]);
                aN[i] = ffma2(v[i], w2, aN[i]);
            }
        }
    };

    LD(0); ST(sb[0]);
#pragma unroll 1
    for (int bi = 0; bi < NB; ++bi) {
        __syncthreads();
        if (bi + 1 < NB) LD(bi + 1);
        CP(sb[bi & 1]);
        if (bi + 1 < NB) ST(sb[(bi + 1) & 1]);
    }
}

// ---------------- encoder step: fused [x_t|h] GEMM + GRU pointwise ----------------
__global__ __launch_bounds__(128, 4)
void enc_step_kernel(const float* __restrict__ x, const float* __restrict__ h0,
                     const float* __restrict__ Wih, const float* __restrict__ Whh,
                     const float* __restrict__ bih, const float* __restrict__ bhh,
                     int t)
{
    __shared__ PipeBuf sb[2];
    int tid = threadIdx.x, warp = tid >> 5, lane = tid & 31;
    int bm0 = blockIdx.x * 16, u0 = blockIdx.y * 64;

    const float* h_prev = (t == 0) ? h0 : (g_hs + (size_t)(t - 1) * Bsz * Hh);
    float*  h_out  = g_hs   + (size_t)t * Bsz * Hh;
    __half* hh_out = g_hs_h + (size_t)t * Bsz * Hh;

    const float* xin = x + (size_t)t * Fin + (size_t)bm0 * (Tin * Fin);
    const float* hin = h_prev + (size_t)bm0 * Hh;

    ull aR[4] = {0}, aZ[4] = {0}, aNX[4] = {0}, aNH[4] = {0};
    gemm_pipe<4> (xin, Tin * Fin, Wih, Fin, u0, tid, warp, lane, aR, aZ, aNX, sb);
    gemm_pipe<16>(hin, Hh,        Whh, Hh,  u0, tid, warp, lane, aR, aZ, aNH, sb);

    int u = u0 + 2 * lane;
    float2 bir = *(const float2*)&bih[u];
    float2 biz = *(const float2*)&bih[256 + u];
    float2 bin = *(const float2*)&bih[512 + u];
    float2 bhr = *(const float2*)&bhh[u];
    float2 bhz = *(const float2*)&bhh[256 + u];
    float2 bhn = *(const float2*)&bhh[512 + u];
#pragma unroll
    for (int i = 0; i < 4; ++i) {
        int b = bm0 + (warp << 2) + i;
        float r0, r1, z0, z1, nx0, nx1, nh0, nh1;
        upk2(aR[i], r0, r1);  upk2(aZ[i], z0, z1);
        upk2(aNX[i], nx0, nx1); upk2(aNH[i], nh0, nh1);
        float2 hp = *(const float2*)&h_prev[(size_t)b * Hh + u];
        float rr0 = sigm(r0 + bir.x + bhr.x);
        float rr1 = sigm(r1 + bir.y + bhr.y);
        float zz0 = sigm(z0 + biz.x + bhz.x);
        float zz1 = sigm(z1 + biz.y + bhz.y);
        float nn0 = tanh_(nx0 + bin.x + rr0 * (nh0 + bhn.x));
        float nn1 = tanh_(nx1 + bin.y + rr1 * (nh1 + bhn.y));
        float2 o;
        o.x = (1.f - zz0) * nn0 + zz0 * hp.x;
        o.y = (1.f - zz1) * nn1 + zz1 * hp.y;
        *(float2*)&h_out[(size_t)b * Hh + u] = o;
        *(__half2*)&hh_out[(size_t)b * Hh + u] = __float22half2_rn(o);
    }
}

// ---------------- attention precompute: A = Wq.hs, C = bq.hs ----------------
__global__ __launch_bounds__(256)
void attn_pre_kernel(const float* __restrict__ Wq, const float* __restrict__ bq)
{
    int warp = threadIdx.x >> 5, lane = threadIdx.x & 31;
    int p = blockIdx.x * 8 + warp;
    int b = p >> 7, t = p & 127;
    const float* hp = g_hs + ((size_t)t * Bsz + b) * Hh;
    float a = 0.f, c = 0.f;
#pragma unroll
    for (int j = 0; j < 8; ++j) {
        int h = lane + 32 * j;
        float v = hp[h];
        a = fmaf(Wq[h], v, a);
        c = fmaf(bq[h], v, c);
    }
#pragma unroll
    for (int off = 16; off > 0; off >>= 1) {
        a += __shfl_xor_sync(0xffffffffu, a, off);
        c += __shfl_xor_sync(0xffffffffu, c, off);
    }
    if (lane == 0) { g_A[(size_t)b * Tin + t] = a; g_C[(size_t)b * Tin + t] = c; }
}

__global__ void init_prev_kernel(const float* __restrict__ x)
{
    int i = blockIdx.x * 256 + threadIdx.x;
    if (i < Bsz) g_prev[i] = x[(size_t)i * Tin * Fin + (size_t)(Tin - 1) * Fin];
}

// ---------------- decoder attention: softmax + fp16 ctx stream ----------------
// 4 rows/CTA -> 512 CTAs; warp w owns row w's softmax; thread owns h-pair 2*tid.
__global__ __launch_bounds__(128)
void dec_attn_kernel()
{
    __shared__ float wbuf[4][128];
    int tid = threadIdx.x, warp = tid >> 5, lane = tid & 31;
    int b0 = blockIdx.x * 4;
    const float scale = 0.0625f;

    {
        int b = b0 + warp;
        float p = g_prev[b];
        float sv[4]; float m = -1e30f;
#pragma unroll
        for (int j = 0; j < 4; ++j) {
            int t = lane + 32 * j;
            sv[j] = scale * fmaf(p, g_A[(size_t)b * Tin + t], g_C[(size_t)b * Tin + t]);
            m = fmaxf(m, sv[j]);
        }
#pragma unroll
        for (int off = 16; off > 0; off >>= 1)
            m = fmaxf(m, __shfl_xor_sync(0xffffffffu, m, off));
        float sum = 0.f;
#pragma unroll
        for (int j = 0; j < 4; ++j) { sv[j] = __expf(sv[j] - m); sum += sv[j]; }
#pragma unroll
        for (int off = 16; off > 0; off >>= 1)
            sum += __shfl_xor_sync(0xffffffffu, sum, off);
        float inv = 1.f / sum;
#pragma unroll
        for (int j = 0; j < 4; ++j) wbuf[warp][lane + 32 * j] = sv[j] * inv;
    }
    __syncthreads();

    float ax[4], ay[4];
#pragma unroll
    for (int r = 0; r < 4; ++r) { ax[r] = 0.f; ay[r] = 0.f; }
#pragma unroll 4
    for (int t = 0; t < Tin; ++t) {
        const __half* hp = g_hs_h + ((size_t)t * Bsz + b0) * Hh + 2 * tid;
#pragma unroll
        for (int r = 0; r < 4; ++r) {
            float w = wbuf[r][t];
            float2 hv = __half22float2(*(const __half2*)(hp + (size_t)r * Hh));
            ax[r] = fmaf(w, hv.x, ax[r]);
            ay[r] = fmaf(w, hv.y, ay[r]);
        }
    }
#pragma unroll
    for (int r = 0; r < 4; ++r) {
        float2 o; o.x = ax[r]; o.y = ay[r];
        *(float2*)&g_ctx[(size_t)(b0 + r) * Hh + 2 * tid] = o;
    }
}

// ---------------- decoder GRU: gh = ctx @ Whh^T (rank-1 gi from prev) ----------------
__global__ __launch_bounds__(128, 4)
void dec_gru_kernel(const float* __restrict__ Wih1, const float* __restrict__ Whh,
                    const float* __restrict__ bih,  const float* __restrict__ bhh)
{
    __shared__ PipeBuf sb[2];
    int tid = threadIdx.x, warp = tid >> 5, lane = tid & 31;
    int bm0 = blockIdx.x * 16, u0 = blockIdx.y * 64;

    ull aR[4] = {0}, aZ[4] = {0}, aN[4] = {0};
    gemm_pipe<16>(g_ctx + (size_t)bm0 * Hh, Hh, Whh, Hh, u0,
                  tid, warp, lane, aR, aZ, aN, sb);

    int u = u0 + 2 * lane;
    float2 wir = *(const float2*)&Wih1[u];
    float2 wiz = *(const float2*)&Wih1[256 + u];
    float2 win = *(const float2*)&Wih1[512 + u];
    float2 bir = *(const float2*)&bih[u];
    float2 biz = *(const float2*)&bih[256 + u];
    float2 bin = *(const float2*)&bih[512 + u];
    float2 bhr = *(const float2*)&bhh[u];
    float2 bhz = *(const float2*)&bhh[256 + u];
    float2 bhn = *(const float2*)&bhh[512 + u];
#pragma unroll
    for (int i = 0; i < 4; ++i) {
        int b = bm0 + (warp << 2) + i;
        float p = g_prev[b];
        float hr0, hr1, hz0, hz1, hn0, hn1;
        upk2(aR[i], hr0, hr1); upk2(aZ[i], hz0, hz1); upk2(aN[i], hn0, hn1);
        float2 c = *(const float2*)&g_ctx[(size_t)b * Hh + u];
        float r0 = sigm(fmaf(p, wir.x, bir.x) + hr0 + bhr.x);
        float r1 = sigm(fmaf(p, wir.y, bir.y) + hr1 + bhr.y);
        float z0 = sigm(fmaf(p, wiz.x, biz.x) + hz0 + bhz.x);
        float z1 = sigm(fmaf(p, wiz.y, biz.y) + hz1 + bhz.y);
        float n0 = tanh_(fmaf(p, win.x, bin.x) + r0 * (hn0 + bhn.x));
        float n1 = tanh_(fmaf(p, win.y, bin.y) + r1 * (hn1 + bhn.y));
        float2 o;
        o.x = (1.f - z0) * n0 + z0 * c.x;
        o.y = (1.f - z1) * n1 + z1 * c.y;
        *(float2*)&g_hd[(size_t)b * Hh + u] = o;
    }
}

// ---------------- decoder output: relu(hd@fc1^T+b) @ fc2^T + b ----------------
__global__ __launch_bounds__(256)
void dec_out_kernel(const float* __restrict__ fc1W, const float* __restrict__ fc1b,
                    const float* __restrict__ fc2W, const float* __restrict__ fc2b,
                    float* __restrict__ out, int step)
{
    __shared__ float hds[8][256];
    __shared__ float wsm[32][257];   // pad 257: store banks = k (conflict-free)
    __shared__ float red[8][8];
    int tid = threadIdx.x, warp = tid >> 5, lane = tid & 31;
    int b0 = blockIdx.x * 8;

    for (int idx = tid; idx < 8 * 256; idx += 256) {
        int row = idx >> 8, k = idx & 255;
        hds[row][k] = g_hd[(size_t)(b0 + row) * 256 + k];
    }

    float acc[8] = {0, 0, 0, 0, 0, 0, 0, 0};
    for (int kb = 0; kb < 256; kb += 32) {
        __syncthreads();
        for (int idx = tid; idx < 32 * 256; idx += 256) {
            int j = idx >> 5, k = idx & 31;
            wsm[k][j] = fc1W[(size_t)j * 256 + kb + k];
        }
        __syncthreads();
#pragma unroll
        for (int k = 0; k < 32; ++k) {
            float wv = wsm[k][tid];
#pragma unroll
            for (int r = 0; r < 8; ++r)
                acc[r] = fmaf(hds[r][kb + k], wv, acc[r]);
        }
    }

    float b1 = fc1b[tid];
    float w2 = fc2W[tid];
#pragma unroll
    for (int r = 0; r < 8; ++r) {
        float v = fmaxf(acc[r] + b1, 0.f) * w2;
#pragma unroll
        for (int off = 16; off > 0; off >>= 1)
            v += __shfl_xor_sync(0xffffffffu, v, off);
        if (lane == 0) red[warp][r] = v;
    }
    __syncthreads();
    if (warp == 0 && lane < 8) {
        int r = lane;
        float ssum = 0.f;
#pragma unroll
        for (int w = 0; w < 8; ++w) ssum += red[w][r];
        ssum += fc2b[0];
        int b = b0 + r;
        out[(size_t)b * OUTL + step] = ssum;
        g_prev[b] = ssum;
    }
}

// ---------------- launch ----------------
extern "C" void kernel_launch(void* const* d_in, const int* in_sizes, int n_in,
                              void* d_out, int out_size)
{
    (void)in_sizes; (void)n_in; (void)out_size;
    const float* x    = (const float*)d_in[0];
    const float* h0   = (const float*)d_in[1];
    const float* eWih = (const float*)d_in[2];
    const float* eWhh = (const float*)d_in[3];
    const float* ebih = (const float*)d_in[4];
    const float* ebhh = (const float*)d_in[5];
    const float* dWih = (const float*)d_in[6];
    const float* dWhh = (const float*)d_in[7];
    const float* dbih = (const float*)d_in[8];
    const float* dbhh = (const float*)d_in[9];
    const float* aWq  = (const float*)d_in[10];
    const float* abq  = (const float*)d_in[11];
    const float* f1W  = (const float*)d_in[12];
    const float* f1b  = (const float*)d_in[13];
    const float* f2W  = (const float*)d_in[14];
    const float* f2b  = (const float*)d_in[15];
    float* out = (float*)d_out;

    dim3 gg(Bsz / 16, Hh / 64);   // (128,4) = 512 CTAs, 128 threads

    for (int t = 0; t < Tin; ++t)
        enc_step_kernel<<<gg, 128>>>(x, h0, eWih, eWhh, ebih, ebhh, t);

    attn_pre_kernel<<<(Bsz * Tin) / 8, 256>>>(aWq, abq);
    init_prev_kernel<<<Bsz / 256, 256>>>(x);

    for (int s = 0; s < OUTL; ++s) {
        dec_attn_kernel<<<Bsz / 4, 128>>>();
        dec_gru_kernel<<<gg, 128>>>(dWih, dWhh, dbih, dbhh);
        dec_out_kernel<<<Bsz / 8, 256>>>(f1W, f1b, f2W, f2b, out, s);
    }
}